// round 2
// baseline (speedup 1.0000x reference)
#include <cuda_runtime.h>
#include <math.h>

#define B_   16
#define LQ   4096
#define LK   4096
#define DD   64
#define BM   64
#define BN   64

// Flash attention fp32 SIMT baseline.
// Grid: (LQ/BM, B). Block: 256 threads.
// Thread (ty = tid>>4, tx = tid&15):
//   S tile rows r = 4*ty+i (i=0..3), cols c = tx+16*j (j=0..3)
//   O tile rows r = 4*ty+i,          cols d = 4*tx+j
// Shared memory (XOR-swizzled, float4 granularity, 16KB each):
//   Qs[64][16f4], Ks[64][16f4], Vs[64][16f4], Ps = P^T stored [n][r/4]
__global__ __launch_bounds__(256, 2)
void fattn_kernel(const float* __restrict__ Q, const float* __restrict__ K,
                  const float* __restrict__ V, const float* __restrict__ scale,
                  float* __restrict__ Out)
{
    extern __shared__ float4 sm4[];
    float4* Qs = sm4;            // [row][ (c4 ^ (row&7)) ]
    float4* Ks = sm4 + 1024;
    float4* Vs = sm4 + 2048;
    float4* Ps = sm4 + 3072;     // P^T: [n][ (ty ^ (n&7)) ], component = i

    const int tid = threadIdx.x;
    const int ty  = tid >> 4;
    const int tx  = tid & 15;
    const int b   = blockIdx.y;
    const int q0  = blockIdx.x * BM;

    const float inv_scale = 1.0f / scale[0];

    const float* Qg = Q + ((size_t)b * LQ + q0) * DD;
    const float* Kg = K + (size_t)b * LK * DD;
    const float* Vg = V + (size_t)b * LK * DD;

    // tile loader: 256 threads, each loads 4 float4s -> 64 rows x 16 float4 cols
    const int lr  = tid >> 4;    // 0..15
    const int lc4 = tid & 15;    // 0..15

    // Q tile (loaded once)
    #pragma unroll
    for (int rr = 0; rr < 4; ++rr) {
        const int row = lr + 16 * rr;
        Qs[row * 16 + (lc4 ^ (row & 7))] = *(const float4*)(Qg + (size_t)row * DD + lc4 * 4);
    }

    float o[4][4];
    float m_i[4], l_i[4];
    #pragma unroll
    for (int i = 0; i < 4; ++i) {
        m_i[i] = -INFINITY;
        l_i[i] = 0.0f;
        #pragma unroll
        for (int j = 0; j < 4; ++j) o[i][j] = 0.0f;
    }

    for (int n0 = 0; n0 < LK; n0 += BN) {
        __syncthreads();   // protect Ks/Vs/Ps from prior-iter reads; covers Qs on iter 0
        #pragma unroll
        for (int rr = 0; rr < 4; ++rr) {
            const int row  = lr + 16 * rr;
            const int slot = row * 16 + (lc4 ^ (row & 7));
            Ks[slot] = *(const float4*)(Kg + (size_t)(n0 + row) * DD + lc4 * 4);
            Vs[slot] = *(const float4*)(Vg + (size_t)(n0 + row) * DD + lc4 * 4);
        }
        __syncthreads();

        // ---- GEMM1: S[r][c] = sum_d Q[r][d] * K[c][d] ----
        float s[4][4];
        #pragma unroll
        for (int i = 0; i < 4; ++i)
            #pragma unroll
            for (int j = 0; j < 4; ++j) s[i][j] = 0.0f;

        #pragma unroll
        for (int d4 = 0; d4 < 16; ++d4) {
            float4 qf[4], kf[4];
            #pragma unroll
            for (int i = 0; i < 4; ++i) {
                const int r = 4 * ty + i;
                qf[i] = Qs[r * 16 + (d4 ^ (r & 7))];
            }
            #pragma unroll
            for (int j = 0; j < 4; ++j) {
                const int c = tx + 16 * j;
                kf[j] = Ks[c * 16 + (d4 ^ (c & 7))];
            }
            #pragma unroll
            for (int i = 0; i < 4; ++i) {
                #pragma unroll
                for (int j = 0; j < 4; ++j) {
                    s[i][j] = fmaf(qf[i].x, kf[j].x, s[i][j]);
                    s[i][j] = fmaf(qf[i].y, kf[j].y, s[i][j]);
                    s[i][j] = fmaf(qf[i].z, kf[j].z, s[i][j]);
                    s[i][j] = fmaf(qf[i].w, kf[j].w, s[i][j]);
                }
            }
        }

        // ---- online softmax (per row, reduced across 16 tx lanes) ----
        #pragma unroll
        for (int i = 0; i < 4; ++i) {
            #pragma unroll
            for (int j = 0; j < 4; ++j) s[i][j] *= inv_scale;

            float mt = fmaxf(fmaxf(s[i][0], s[i][1]), fmaxf(s[i][2], s[i][3]));
            #pragma unroll
            for (int d = 1; d < 16; d <<= 1)
                mt = fmaxf(mt, __shfl_xor_sync(0xffffffffu, mt, d));

            const float mn   = fmaxf(m_i[i], mt);
            const float corr = __expf(m_i[i] - mn);   // 0 on first tile (exp(-inf))
            m_i[i] = mn;

            float p[4];
            float ls = 0.0f;
            #pragma unroll
            for (int j = 0; j < 4; ++j) { p[j] = __expf(s[i][j] - mn); ls += p[j]; }
            #pragma unroll
            for (int d = 1; d < 16; d <<= 1)
                ls += __shfl_xor_sync(0xffffffffu, ls, d);

            l_i[i] = l_i[i] * corr + ls;
            #pragma unroll
            for (int j = 0; j < 4; ++j) o[i][j] *= corr;

            // store P^T[n=c][r=4ty+i]
            #pragma unroll
            for (int j = 0; j < 4; ++j) {
                const int c = tx + 16 * j;
                ((float*)Ps)[(c * 16 + (ty ^ (c & 7))) * 4 + i] = p[j];
            }
        }
        __syncthreads();

        // ---- GEMM2: O[r][d] += sum_n P[r][n] * V[n][d] ----
        #pragma unroll
        for (int n4 = 0; n4 < 16; ++n4) {
            #pragma unroll
            for (int nn = 0; nn < 4; ++nn) {
                const int n = 4 * n4 + nn;
                const float4 pf = Ps[n * 16 + (ty ^ (n & 7))];  // P[4ty..4ty+3][n]
                const float4 vf = Vs[n * 16 + (tx ^ (n & 7))];  // V[n][4tx..4tx+3]
                const float pr[4] = {pf.x, pf.y, pf.z, pf.w};
                const float vr[4] = {vf.x, vf.y, vf.z, vf.w};
                #pragma unroll
                for (int i = 0; i < 4; ++i)
                    #pragma unroll
                    for (int j = 0; j < 4; ++j)
                        o[i][j] = fmaf(pr[i], vr[j], o[i][j]);
            }
        }
    }

    // ---- epilogue: normalize and store ----
    float* Og = Out + ((size_t)b * LQ + q0) * DD;
    #pragma unroll
    for (int i = 0; i < 4; ++i) {
        const float inv_l = 1.0f / l_i[i];
        const int r = 4 * ty + i;
        float4 res;
        res.x = o[i][0] * inv_l;
        res.y = o[i][1] * inv_l;
        res.z = o[i][2] * inv_l;
        res.w = o[i][3] * inv_l;
        *(float4*)(Og + (size_t)r * DD + 4 * tx) = res;
    }
}

extern "C" void kernel_launch(void* const* d_in, const int* in_sizes, int n_in,
                              void* d_out, int out_size)
{
    const float* Q     = (const float*)d_in[0];
    const float* K     = (const float*)d_in[1];
    const float* V     = (const float*)d_in[2];
    const float* scale = (const float*)d_in[3];
    float* O           = (float*)d_out;

    // 64KB dynamic smem (> 48KB default cap). Host-side attribute set; not a
    // stream op, safe under graph capture, idempotent.
    cudaFuncSetAttribute(fattn_kernel, cudaFuncAttributeMaxDynamicSharedMemorySize, 65536);

    dim3 grid(LQ / BM, B_);
    fattn_kernel<<<grid, 256, 65536>>>(Q, K, V, scale, O);
}

// round 3
// speedup vs baseline: 1.0580x; 1.0580x over previous
#include <cuda_runtime.h>
#include <math.h>

#define B_   16
#define LQ   4096
#define LK   4096
#define DD   64
#define BM   64
#define BN   64

// Flash attention fp32 SIMT baseline.
// Grid: (LQ/BM, B). Block: 256 threads.
// Thread (ty = tid>>4, tx = tid&15):
//   S tile rows r = 4*ty+i (i=0..3), cols c = tx+16*j (j=0..3)
//   O tile rows r = 4*ty+i,          cols d = 4*tx+j
// Shared memory (XOR-swizzled, float4 granularity, 16KB each):
//   Qs[64][16f4], Ks[64][16f4], Vs[64][16f4], Ps = P^T stored [n][r/4]
__global__ __launch_bounds__(256, 2)
void fattn_kernel(const float* __restrict__ Q, const float* __restrict__ K,
                  const float* __restrict__ V, const float* __restrict__ scale,
                  float* __restrict__ Out)
{
    extern __shared__ float4 sm4[];
    float4* Qs = sm4;            // [row][ (c4 ^ (row&7)) ]
    float4* Ks = sm4 + 1024;
    float4* Vs = sm4 + 2048;
    float4* Ps = sm4 + 3072;     // P^T: [n][ (ty ^ (n&7)) ], component = i

    const int tid = threadIdx.x;
    const int ty  = tid >> 4;
    const int tx  = tid & 15;
    const int b   = blockIdx.y;
    const int q0  = blockIdx.x * BM;

    const float inv_scale = 1.0f / scale[0];

    const float* Qg = Q + ((size_t)b * LQ + q0) * DD;
    const float* Kg = K + (size_t)b * LK * DD;
    const float* Vg = V + (size_t)b * LK * DD;

    // tile loader: 256 threads, each loads 4 float4s -> 64 rows x 16 float4 cols
    const int lr  = tid >> 4;    // 0..15
    const int lc4 = tid & 15;    // 0..15

    // Q tile (loaded once)
    #pragma unroll
    for (int rr = 0; rr < 4; ++rr) {
        const int row = lr + 16 * rr;
        Qs[row * 16 + (lc4 ^ (row & 7))] = *(const float4*)(Qg + (size_t)row * DD + lc4 * 4);
    }

    float o[4][4];
    float m_i[4], l_i[4];
    #pragma unroll
    for (int i = 0; i < 4; ++i) {
        m_i[i] = -INFINITY;
        l_i[i] = 0.0f;
        #pragma unroll
        for (int j = 0; j < 4; ++j) o[i][j] = 0.0f;
    }

    for (int n0 = 0; n0 < LK; n0 += BN) {
        __syncthreads();   // protect Ks/Vs/Ps from prior-iter reads; covers Qs on iter 0
        #pragma unroll
        for (int rr = 0; rr < 4; ++rr) {
            const int row  = lr + 16 * rr;
            const int slot = row * 16 + (lc4 ^ (row & 7));
            Ks[slot] = *(const float4*)(Kg + (size_t)(n0 + row) * DD + lc4 * 4);
            Vs[slot] = *(const float4*)(Vg + (size_t)(n0 + row) * DD + lc4 * 4);
        }
        __syncthreads();

        // ---- GEMM1: S[r][c] = sum_d Q[r][d] * K[c][d] ----
        float s[4][4];
        #pragma unroll
        for (int i = 0; i < 4; ++i)
            #pragma unroll
            for (int j = 0; j < 4; ++j) s[i][j] = 0.0f;

        #pragma unroll
        for (int d4 = 0; d4 < 16; ++d4) {
            float4 qf[4], kf[4];
            #pragma unroll
            for (int i = 0; i < 4; ++i) {
                const int r = 4 * ty + i;
                qf[i] = Qs[r * 16 + (d4 ^ (r & 7))];
            }
            #pragma unroll
            for (int j = 0; j < 4; ++j) {
                const int c = tx + 16 * j;
                kf[j] = Ks[c * 16 + (d4 ^ (c & 7))];
            }
            #pragma unroll
            for (int i = 0; i < 4; ++i) {
                #pragma unroll
                for (int j = 0; j < 4; ++j) {
                    s[i][j] = fmaf(qf[i].x, kf[j].x, s[i][j]);
                    s[i][j] = fmaf(qf[i].y, kf[j].y, s[i][j]);
                    s[i][j] = fmaf(qf[i].z, kf[j].z, s[i][j]);
                    s[i][j] = fmaf(qf[i].w, kf[j].w, s[i][j]);
                }
            }
        }

        // ---- online softmax (per row, reduced across 16 tx lanes) ----
        #pragma unroll
        for (int i = 0; i < 4; ++i) {
            #pragma unroll
            for (int j = 0; j < 4; ++j) s[i][j] *= inv_scale;

            float mt = fmaxf(fmaxf(s[i][0], s[i][1]), fmaxf(s[i][2], s[i][3]));
            #pragma unroll
            for (int d = 1; d < 16; d <<= 1)
                mt = fmaxf(mt, __shfl_xor_sync(0xffffffffu, mt, d));

            const float mn   = fmaxf(m_i[i], mt);
            const float corr = __expf(m_i[i] - mn);   // 0 on first tile (exp(-inf))
            m_i[i] = mn;

            float p[4];
            float ls = 0.0f;
            #pragma unroll
            for (int j = 0; j < 4; ++j) { p[j] = __expf(s[i][j] - mn); ls += p[j]; }
            #pragma unroll
            for (int d = 1; d < 16; d <<= 1)
                ls += __shfl_xor_sync(0xffffffffu, ls, d);

            l_i[i] = l_i[i] * corr + ls;
            #pragma unroll
            for (int j = 0; j < 4; ++j) o[i][j] *= corr;

            // store P^T[n=c][r=4ty+i]
            #pragma unroll
            for (int j = 0; j < 4; ++j) {
                const int c = tx + 16 * j;
                ((float*)Ps)[(c * 16 + (ty ^ (c & 7))) * 4 + i] = p[j];
            }
        }
        __syncthreads();

        // ---- GEMM2: O[r][d] += sum_n P[r][n] * V[n][d] ----
        #pragma unroll
        for (int n4 = 0; n4 < 16; ++n4) {
            #pragma unroll
            for (int nn = 0; nn < 4; ++nn) {
                const int n = 4 * n4 + nn;
                const float4 pf = Ps[n * 16 + (ty ^ (n & 7))];  // P[4ty..4ty+3][n]
                const float4 vf = Vs[n * 16 + (tx ^ (n & 7))];  // V[n][4tx..4tx+3]
                const float pr[4] = {pf.x, pf.y, pf.z, pf.w};
                const float vr[4] = {vf.x, vf.y, vf.z, vf.w};
                #pragma unroll
                for (int i = 0; i < 4; ++i)
                    #pragma unroll
                    for (int j = 0; j < 4; ++j)
                        o[i][j] = fmaf(pr[i], vr[j], o[i][j]);
            }
        }
    }

    // ---- epilogue: normalize and store ----
    float* Og = Out + ((size_t)b * LQ + q0) * DD;
    #pragma unroll
    for (int i = 0; i < 4; ++i) {
        const float inv_l = 1.0f / l_i[i];
        const int r = 4 * ty + i;
        float4 res;
        res.x = o[i][0] * inv_l;
        res.y = o[i][1] * inv_l;
        res.z = o[i][2] * inv_l;
        res.w = o[i][3] * inv_l;
        *(float4*)(Og + (size_t)r * DD + 4 * tx) = res;
    }
}

extern "C" void kernel_launch(void* const* d_in, const int* in_sizes, int n_in,
                              void* d_out, int out_size)
{
    const float* Q     = (const float*)d_in[0];
    const float* K     = (const float*)d_in[1];
    const float* V     = (const float*)d_in[2];
    const float* scale = (const float*)d_in[3];
    float* O           = (float*)d_out;

    // 64KB dynamic smem (> 48KB default cap). Host-side attribute set; not a
    // stream op, safe under graph capture, idempotent.
    cudaFuncSetAttribute(fattn_kernel, cudaFuncAttributeMaxDynamicSharedMemorySize, 65536);

    dim3 grid(LQ / BM, B_);
    fattn_kernel<<<grid, 256, 65536>>>(Q, K, V, scale, O);
}

// round 5
// speedup vs baseline: 3.3504x; 3.1668x over previous
#include <cuda_runtime.h>
#include <cuda_fp16.h>
#include <stdint.h>
#include <math.h>

#define B_   16
#define LQ   4096
#define LK   4096
#define DD   64
#define BMq  64
#define BN   64
#define NT   (LK / BN)

__device__ __forceinline__ void ldsm4(uint32_t r[4], uint32_t a) {
    asm volatile("ldmatrix.sync.aligned.m8n8.x4.shared.b16 {%0,%1,%2,%3}, [%4];"
                 : "=r"(r[0]), "=r"(r[1]), "=r"(r[2]), "=r"(r[3]) : "r"(a));
}
__device__ __forceinline__ void ldsm4t(uint32_t r[4], uint32_t a) {
    asm volatile("ldmatrix.sync.aligned.m8n8.x4.trans.shared.b16 {%0,%1,%2,%3}, [%4];"
                 : "=r"(r[0]), "=r"(r[1]), "=r"(r[2]), "=r"(r[3]) : "r"(a));
}
__device__ __forceinline__ void hmma(float c[4], const uint32_t a[4], uint32_t b0, uint32_t b1) {
    asm volatile("mma.sync.aligned.m16n8k16.row.col.f32.f16.f16.f32 "
                 "{%0,%1,%2,%3}, {%4,%5,%6,%7}, {%8,%9}, {%0,%1,%2,%3};"
                 : "+f"(c[0]), "+f"(c[1]), "+f"(c[2]), "+f"(c[3])
                 : "r"(a[0]), "r"(a[1]), "r"(a[2]), "r"(a[3]), "r"(b0), "r"(b1));
}
__device__ __forceinline__ uint32_t smem_u32(const void* p) {
    uint32_t a;
    asm("{ .reg .u64 t; cvta.to.shared.u64 t, %1; cvt.u32.u64 %0, t; }" : "=r"(a) : "l"(p));
    return a;
}
// swizzled byte offset within a 64x64 fp16 tile: row stride 128B, 16B chunks XOR'ed by row&7
__device__ __forceinline__ uint32_t swoff(int row, int ch) {
    return (uint32_t)(row * 128 + ((ch ^ (row & 7)) << 4));
}
__device__ __forceinline__ uint32_t h2u(__half2 h) { return *reinterpret_cast<uint32_t*>(&h); }

__global__ __launch_bounds__(128, 2)
void fattn_hmma(const float* __restrict__ Qp, const float* __restrict__ Kp,
                const float* __restrict__ Vp, const float* __restrict__ scale,
                float* __restrict__ Out)
{
    __shared__ __align__(128) uint8_t sm[24576];   // KH 8K | KL 8K | VH 8K
    const uint32_t sb = smem_u32(sm);
    const uint32_t KH = sb, KL = sb + 8192, VH = sb + 16384;

    const int tid  = threadIdx.x;
    const int w    = tid >> 5;
    const int lane = tid & 31;
    const int gh   = (lane >> 4) & 1;       // (lane>>3)>>1
    const int gl   = (lane >> 3) & 1;
    const int lr   = lane & 7;
    const int b    = blockIdx.y;
    const int q0   = blockIdx.x * BMq;

    const float inv_scale = 1.0f / scale[0];

    const float* Qg = Qp + ((size_t)b * LQ + q0) * DD;
    const float* Kg = Kp + (size_t)b * LK * DD;
    const float* Vg = Vp + (size_t)b * LK * DD;

    // ---- stage Q split into KH/KL areas (reused for K after frag load) ----
    #pragma unroll
    for (int i = 0; i < 8; ++i) {
        int idx = tid + i * 128;
        int row = idx >> 4, c4 = idx & 15;
        uint32_t off = (uint32_t)(row * 128 + (((c4 >> 1) ^ (row & 7)) << 4) + (c4 & 1) * 8);
        float4 q = *(const float4*)(Qg + (size_t)row * DD + c4 * 4);
        __half2 h01 = __floats2half2_rn(q.x, q.y), h23 = __floats2half2_rn(q.z, q.w);
        float2 f01 = __half22float2(h01), f23 = __half22float2(h23);
        __half2 L01 = __floats2half2_rn(q.x - f01.x, q.y - f01.y);
        __half2 L23 = __floats2half2_rn(q.z - f23.x, q.w - f23.y);
        *(uint2*)(sm + off)        = make_uint2(h2u(h01), h2u(h23));
        *(uint2*)(sm + 8192 + off) = make_uint2(h2u(L01), h2u(L23));
    }
    __syncthreads();

    // Q A-fragments: rows w*16..+15, 4 k-chunks of 16
    uint32_t aQh[4][4], aQl[4][4];
    #pragma unroll
    for (int kc = 0; kc < 4; ++kc) {
        int row = w * 16 + (gl << 3) + lr;
        int ch  = 2 * kc + gh;
        ldsm4(aQh[kc], KH + swoff(row, ch));
        ldsm4(aQl[kc], KL + swoff(row, ch));
    }

    float o[8][4];
    #pragma unroll
    for (int i = 0; i < 8; ++i) { o[i][0] = o[i][1] = o[i][2] = o[i][3] = 0.0f; }
    float m0 = -INFINITY, m1 = -INFINITY, l0 = 0.0f, l1 = 0.0f;

    for (int t = 0; t < NT; ++t) {
        __syncthreads();   // all warps done reading previous K/V (and Q frags on t=0)
        const float* Kt = Kg + (size_t)t * BN * DD;
        const float* Vt = Vg + (size_t)t * BN * DD;
        #pragma unroll
        for (int i = 0; i < 8; ++i) {
            int idx = tid + i * 128;
            int row = idx >> 4, c4 = idx & 15;
            uint32_t off = (uint32_t)(row * 128 + (((c4 >> 1) ^ (row & 7)) << 4) + (c4 & 1) * 8);
            float4 k = *(const float4*)(Kt + (size_t)row * DD + c4 * 4);
            __half2 h01 = __floats2half2_rn(k.x, k.y), h23 = __floats2half2_rn(k.z, k.w);
            float2 f01 = __half22float2(h01), f23 = __half22float2(h23);
            __half2 L01 = __floats2half2_rn(k.x - f01.x, k.y - f01.y);
            __half2 L23 = __floats2half2_rn(k.z - f23.x, k.w - f23.y);
            *(uint2*)(sm + off)        = make_uint2(h2u(h01), h2u(h23));
            *(uint2*)(sm + 8192 + off) = make_uint2(h2u(L01), h2u(L23));
            float4 v = *(const float4*)(Vt + (size_t)row * DD + c4 * 4);
            __half2 v01 = __floats2half2_rn(v.x, v.y), v23 = __floats2half2_rn(v.z, v.w);
            *(uint2*)(sm + 16384 + off) = make_uint2(h2u(v01), h2u(v23));
        }
        __syncthreads();

        // ---- GEMM1: S = Qh*Kh^T + Ql*Kh^T + Qh*Kl^T ----
        float s[8][4];
        #pragma unroll
        for (int nb2 = 0; nb2 < 4; ++nb2) {
            uint32_t bh[4][4], bl[4][4];
            #pragma unroll
            for (int kc = 0; kc < 4; ++kc) {
                int row = nb2 * 16 + (gh << 3) + lr;
                int ch  = 2 * kc + gl;
                ldsm4(bh[kc], KH + swoff(row, ch));
                ldsm4(bl[kc], KL + swoff(row, ch));
            }
            float* cA = s[2 * nb2];
            float* cB = s[2 * nb2 + 1];
            cA[0] = cA[1] = cA[2] = cA[3] = 0.0f;
            cB[0] = cB[1] = cB[2] = cB[3] = 0.0f;
            #pragma unroll
            for (int kc = 0; kc < 4; ++kc) {
                hmma(cA, aQh[kc], bh[kc][0], bh[kc][1]);
                hmma(cA, aQl[kc], bh[kc][0], bh[kc][1]);
                hmma(cA, aQh[kc], bl[kc][0], bl[kc][1]);
                hmma(cB, aQh[kc], bh[kc][2], bh[kc][3]);
                hmma(cB, aQl[kc], bh[kc][2], bh[kc][3]);
                hmma(cB, aQh[kc], bl[kc][2], bl[kc][3]);
            }
        }

        // ---- online softmax (thread owns rows r and r+8; cols spread over quad lanes) ----
        float mx0 = -INFINITY, mx1 = -INFINITY;
        #pragma unroll
        for (int nb = 0; nb < 8; ++nb) {
            s[nb][0] *= inv_scale; s[nb][1] *= inv_scale;
            s[nb][2] *= inv_scale; s[nb][3] *= inv_scale;
            mx0 = fmaxf(mx0, fmaxf(s[nb][0], s[nb][1]));
            mx1 = fmaxf(mx1, fmaxf(s[nb][2], s[nb][3]));
        }
        mx0 = fmaxf(mx0, __shfl_xor_sync(0xffffffffu, mx0, 1));
        mx0 = fmaxf(mx0, __shfl_xor_sync(0xffffffffu, mx0, 2));
        mx1 = fmaxf(mx1, __shfl_xor_sync(0xffffffffu, mx1, 1));
        mx1 = fmaxf(mx1, __shfl_xor_sync(0xffffffffu, mx1, 2));
        const float mn0 = fmaxf(m0, mx0), mn1 = fmaxf(m1, mx1);
        const float c0 = __expf(m0 - mn0), c1 = __expf(m1 - mn1);
        m0 = mn0; m1 = mn1;
        l0 *= c0;  l1 *= c1;

        uint32_t aPh[4][4], aPl[4][4];
        #pragma unroll
        for (int nb = 0; nb < 8; ++nb) {
            float p0 = __expf(s[nb][0] - mn0), p1 = __expf(s[nb][1] - mn0);
            float p2 = __expf(s[nb][2] - mn1), p3 = __expf(s[nb][3] - mn1);
            l0 += p0 + p1;  l1 += p2 + p3;
            __half2 hA = __floats2half2_rn(p0, p1), hB = __floats2half2_rn(p2, p3);
            float2 fA = __half22float2(hA), fB = __half22float2(hB);
            __half2 lA = __floats2half2_rn(p0 - fA.x, p1 - fA.y);
            __half2 lB = __floats2half2_rn(p2 - fB.x, p3 - fB.y);
            const int kc = nb >> 1, hi = (nb & 1) * 2;
            aPh[kc][hi + 0] = h2u(hA);  aPh[kc][hi + 1] = h2u(hB);
            aPl[kc][hi + 0] = h2u(lA);  aPl[kc][hi + 1] = h2u(lB);
        }
        #pragma unroll
        for (int db = 0; db < 8; ++db) {
            o[db][0] *= c0; o[db][1] *= c0; o[db][2] *= c1; o[db][3] *= c1;
        }

        // ---- GEMM2: O += Ph*V + Pl*V ----
        #pragma unroll
        for (int db2 = 0; db2 < 4; ++db2) {
            uint32_t bv[4][4];
            #pragma unroll
            for (int kc = 0; kc < 4; ++kc) {
                int row = kc * 16 + (gl << 3) + lr;
                int ch  = 2 * db2 + gh;
                ldsm4t(bv[kc], VH + swoff(row, ch));
            }
            #pragma unroll
            for (int kc = 0; kc < 4; ++kc) {
                hmma(o[2 * db2],     aPh[kc], bv[kc][0], bv[kc][1]);
                hmma(o[2 * db2],     aPl[kc], bv[kc][0], bv[kc][1]);
                hmma(o[2 * db2 + 1], aPh[kc], bv[kc][2], bv[kc][3]);
                hmma(o[2 * db2 + 1], aPl[kc], bv[kc][2], bv[kc][3]);
            }
        }
    }

    // ---- epilogue ----
    l0 += __shfl_xor_sync(0xffffffffu, l0, 1);
    l0 += __shfl_xor_sync(0xffffffffu, l0, 2);
    l1 += __shfl_xor_sync(0xffffffffu, l1, 1);
    l1 += __shfl_xor_sync(0xffffffffu, l1, 2);
    const float inv0 = 1.0f / l0, inv1 = 1.0f / l1;

    const int r0 = q0 + w * 16 + (lane >> 2);
    const int dc = 2 * (lane & 3);
    float* O0 = Out + ((size_t)b * LQ + r0) * DD;
    float* O1 = O0 + 8 * DD;
    #pragma unroll
    for (int db = 0; db < 8; ++db) {
        *(float2*)(O0 + db * 8 + dc) = make_float2(o[db][0] * inv0, o[db][1] * inv0);
        *(float2*)(O1 + db * 8 + dc) = make_float2(o[db][2] * inv1, o[db][3] * inv1);
    }
}

extern "C" void kernel_launch(void* const* d_in, const int* in_sizes, int n_in,
                              void* d_out, int out_size)
{
    const float* Q     = (const float*)d_in[0];
    const float* K     = (const float*)d_in[1];
    const float* V     = (const float*)d_in[2];
    const float* scale = (const float*)d_in[3];
    float* O           = (float*)d_out;

    dim3 grid(LQ / BMq, B_);
    fattn_hmma<<<grid, 128>>>(Q, K, V, scale, O);
}

// round 6
// speedup vs baseline: 3.8711x; 1.1554x over previous
#include <cuda_runtime.h>
#include <cuda_fp16.h>
#include <stdint.h>
#include <math.h>

#define B_   16
#define LQ   4096
#define LK   4096
#define DD   64
#define BMq  64
#define BN   64
#define NT   (LK / BN)

// dynamic smem layout (bytes)
#define OFF_QH 0
#define OFF_QL 8192
#define OFF_KH 16384
#define OFF_KL 24576
#define OFF_VH 32768
#define OFF_SK 40960     // raw fp32 K staging (16KB)
#define OFF_SV 57344     // raw fp32 V staging (16KB)
#define SM_TOTAL 73728   // 72KB

__device__ __forceinline__ void ldsm4(uint32_t r[4], uint32_t a) {
    asm volatile("ldmatrix.sync.aligned.m8n8.x4.shared.b16 {%0,%1,%2,%3}, [%4];"
                 : "=r"(r[0]), "=r"(r[1]), "=r"(r[2]), "=r"(r[3]) : "r"(a));
}
__device__ __forceinline__ void ldsm4t(uint32_t r[4], uint32_t a) {
    asm volatile("ldmatrix.sync.aligned.m8n8.x4.trans.shared.b16 {%0,%1,%2,%3}, [%4];"
                 : "=r"(r[0]), "=r"(r[1]), "=r"(r[2]), "=r"(r[3]) : "r"(a));
}
__device__ __forceinline__ void hmma(float c[4], const uint32_t a[4], uint32_t b0, uint32_t b1) {
    asm volatile("mma.sync.aligned.m16n8k16.row.col.f32.f16.f16.f32 "
                 "{%0,%1,%2,%3}, {%4,%5,%6,%7}, {%8,%9}, {%0,%1,%2,%3};"
                 : "+f"(c[0]), "+f"(c[1]), "+f"(c[2]), "+f"(c[3])
                 : "r"(a[0]), "r"(a[1]), "r"(a[2]), "r"(a[3]), "r"(b0), "r"(b1));
}
__device__ __forceinline__ uint32_t smem_u32(const void* p) {
    uint32_t a;
    asm("{ .reg .u64 t; cvta.to.shared.u64 t, %1; cvt.u32.u64 %0, t; }" : "=r"(a) : "l"(p));
    return a;
}
__device__ __forceinline__ void cpa16(uint32_t dst, const void* src) {
    asm volatile("cp.async.cg.shared.global [%0], [%1], 16;" :: "r"(dst), "l"(src));
}
#define CP_COMMIT() asm volatile("cp.async.commit_group;" ::: "memory")
#define CP_WAIT0()  asm volatile("cp.async.wait_group 0;" ::: "memory")

// swizzled byte offset within a 64x64 fp16 tile: row stride 128B, 16B chunks XOR by row&7
__device__ __forceinline__ uint32_t swoff(int row, int ch) {
    return (uint32_t)(row * 128 + ((ch ^ (row & 7)) << 4));
}
__device__ __forceinline__ uint32_t h2u(__half2 h) { return *reinterpret_cast<uint32_t*>(&h); }

__global__ __launch_bounds__(128, 3)
void fattn_hmma(const float* __restrict__ Qp, const float* __restrict__ Kp,
                const float* __restrict__ Vp, const float* __restrict__ scale,
                float* __restrict__ Out)
{
    extern __shared__ __align__(128) uint8_t sm[];
    const uint32_t sb = smem_u32(sm);
    const uint32_t QHa = sb + OFF_QH, QLa = sb + OFF_QL;
    const uint32_t KHa = sb + OFF_KH, KLa = sb + OFF_KL, VHa = sb + OFF_VH;

    const int tid  = threadIdx.x;
    const int w    = tid >> 5;
    const int lane = tid & 31;
    const int gh   = (lane >> 4) & 1;
    const int gl   = (lane >> 3) & 1;
    const int lr   = lane & 7;
    const int b    = blockIdx.y;
    const int q0   = blockIdx.x * BMq;

    const float inv_scale = 1.0f / scale[0];

    const float* Qg = Qp + ((size_t)b * LQ + q0) * DD;
    const float* Kg = Kp + (size_t)b * LK * DD;
    const float* Vg = Vp + (size_t)b * LK * DD;

    // ---- prologue: prefetch tile 0 K/V into raw staging ----
    #pragma unroll
    for (int i = 0; i < 8; ++i) {
        const int idx = tid + i * 128;         // chunk id 0..1023
        cpa16(sb + OFF_SK + idx * 16, Kg + idx * 4);
        cpa16(sb + OFF_SV + idx * 16, Vg + idx * 4);
    }
    CP_COMMIT();

    // ---- Q load + split into resident QH/QL smem ----
    #pragma unroll
    for (int i = 0; i < 8; ++i) {
        int idx = tid + i * 128;
        int row = idx >> 4, c4 = idx & 15;
        uint32_t off = (uint32_t)(row * 128 + (((c4 >> 1) ^ (row & 7)) << 4) + (c4 & 1) * 8);
        float4 q = *(const float4*)(Qg + (size_t)row * DD + c4 * 4);
        __half2 h01 = __floats2half2_rn(q.x, q.y), h23 = __floats2half2_rn(q.z, q.w);
        float2 f01 = __half22float2(h01), f23 = __half22float2(h23);
        __half2 L01 = __floats2half2_rn(q.x - f01.x, q.y - f01.y);
        __half2 L23 = __floats2half2_rn(q.z - f23.x, q.w - f23.y);
        *(uint2*)(sm + OFF_QH + off) = make_uint2(h2u(h01), h2u(h23));
        *(uint2*)(sm + OFF_QL + off) = make_uint2(h2u(L01), h2u(L23));
    }

    float o[8][4];
    #pragma unroll
    for (int i = 0; i < 8; ++i) { o[i][0] = o[i][1] = o[i][2] = o[i][3] = 0.0f; }
    float m0 = -INFINITY, m1 = -INFINITY, l0 = 0.0f, l1 = 0.0f;

    for (int t = 0; t < NT; ++t) {
        CP_WAIT0();           // this tile's raw K/V arrived (own chunks)
        __syncthreads();      // all warps done reading previous fp16 tiles (and Q stores on t=0)

        // ---- convert own staged chunks -> fp16 KH/KL/VH ----
        #pragma unroll
        for (int i = 0; i < 8; ++i) {
            int idx = tid + i * 128;
            int row = idx >> 4, c4 = idx & 15;
            uint32_t off = (uint32_t)(row * 128 + (((c4 >> 1) ^ (row & 7)) << 4) + (c4 & 1) * 8);
            float4 k = *(const float4*)(sm + OFF_SK + idx * 16);
            __half2 h01 = __floats2half2_rn(k.x, k.y), h23 = __floats2half2_rn(k.z, k.w);
            float2 f01 = __half22float2(h01), f23 = __half22float2(h23);
            __half2 L01 = __floats2half2_rn(k.x - f01.x, k.y - f01.y);
            __half2 L23 = __floats2half2_rn(k.z - f23.x, k.w - f23.y);
            *(uint2*)(sm + OFF_KH + off) = make_uint2(h2u(h01), h2u(h23));
            *(uint2*)(sm + OFF_KL + off) = make_uint2(h2u(L01), h2u(L23));
            float4 v = *(const float4*)(sm + OFF_SV + idx * 16);
            __half2 v01 = __floats2half2_rn(v.x, v.y), v23 = __floats2half2_rn(v.z, v.w);
            *(uint2*)(sm + OFF_VH + off) = make_uint2(h2u(v01), h2u(v23));
        }

        // ---- prefetch next tile into staging (own chunks already consumed) ----
        if (t + 1 < NT) {
            const float* Kn = Kg + (size_t)(t + 1) * BN * DD;
            const float* Vn = Vg + (size_t)(t + 1) * BN * DD;
            #pragma unroll
            for (int i = 0; i < 8; ++i) {
                const int idx = tid + i * 128;
                cpa16(sb + OFF_SK + idx * 16, Kn + idx * 4);
                cpa16(sb + OFF_SV + idx * 16, Vn + idx * 4);
            }
        }
        CP_COMMIT();
        __syncthreads();      // fp16 areas ready for all warps

        // ---- Q A-fragments (from resident smem; frees persistent regs) ----
        uint32_t aQh[4][4], aQl[4][4];
        #pragma unroll
        for (int kc = 0; kc < 4; ++kc) {
            int row = w * 16 + (gl << 3) + lr;
            int ch  = 2 * kc + gh;
            ldsm4(aQh[kc], QHa + swoff(row, ch));
            ldsm4(aQl[kc], QLa + swoff(row, ch));
        }

        // ---- GEMM1: S = Qh*Kh^T + Ql*Kh^T + Qh*Kl^T ----
        float s[8][4];
        #pragma unroll
        for (int nb2 = 0; nb2 < 4; ++nb2) {
            uint32_t bh[4][4], bl[4][4];
            #pragma unroll
            for (int kc = 0; kc < 4; ++kc) {
                int row = nb2 * 16 + (gh << 3) + lr;
                int ch  = 2 * kc + gl;
                ldsm4(bh[kc], KHa + swoff(row, ch));
                ldsm4(bl[kc], KLa + swoff(row, ch));
            }
            float* cA = s[2 * nb2];
            float* cB = s[2 * nb2 + 1];
            cA[0] = cA[1] = cA[2] = cA[3] = 0.0f;
            cB[0] = cB[1] = cB[2] = cB[3] = 0.0f;
            #pragma unroll
            for (int kc = 0; kc < 4; ++kc) {
                hmma(cA, aQh[kc], bh[kc][0], bh[kc][1]);
                hmma(cA, aQl[kc], bh[kc][0], bh[kc][1]);
                hmma(cA, aQh[kc], bl[kc][0], bl[kc][1]);
                hmma(cB, aQh[kc], bh[kc][2], bh[kc][3]);
                hmma(cB, aQl[kc], bh[kc][2], bh[kc][3]);
                hmma(cB, aQh[kc], bl[kc][2], bl[kc][3]);
            }
        }

        // ---- online softmax (thread owns rows r, r+8; cols across quad lanes) ----
        float mx0 = -INFINITY, mx1 = -INFINITY;
        #pragma unroll
        for (int nb = 0; nb < 8; ++nb) {
            s[nb][0] *= inv_scale; s[nb][1] *= inv_scale;
            s[nb][2] *= inv_scale; s[nb][3] *= inv_scale;
            mx0 = fmaxf(mx0, fmaxf(s[nb][0], s[nb][1]));
            mx1 = fmaxf(mx1, fmaxf(s[nb][2], s[nb][3]));
        }
        mx0 = fmaxf(mx0, __shfl_xor_sync(0xffffffffu, mx0, 1));
        mx0 = fmaxf(mx0, __shfl_xor_sync(0xffffffffu, mx0, 2));
        mx1 = fmaxf(mx1, __shfl_xor_sync(0xffffffffu, mx1, 1));
        mx1 = fmaxf(mx1, __shfl_xor_sync(0xffffffffu, mx1, 2));
        const float mn0 = fmaxf(m0, mx0), mn1 = fmaxf(m1, mx1);
        const float c0 = __expf(m0 - mn0), c1 = __expf(m1 - mn1);
        m0 = mn0; m1 = mn1;
        l0 *= c0;  l1 *= c1;

        uint32_t aPh[4][4], aPl[4][4];
        #pragma unroll
        for (int nb = 0; nb < 8; ++nb) {
            float p0 = __expf(s[nb][0] - mn0), p1 = __expf(s[nb][1] - mn0);
            float p2 = __expf(s[nb][2] - mn1), p3 = __expf(s[nb][3] - mn1);
            l0 += p0 + p1;  l1 += p2 + p3;
            __half2 hA = __floats2half2_rn(p0, p1), hB = __floats2half2_rn(p2, p3);
            float2 fA = __half22float2(hA), fB = __half22float2(hB);
            __half2 lA = __floats2half2_rn(p0 - fA.x, p1 - fA.y);
            __half2 lB = __floats2half2_rn(p2 - fB.x, p3 - fB.y);
            const int kc = nb >> 1, hi = (nb & 1) * 2;
            aPh[kc][hi + 0] = h2u(hA);  aPh[kc][hi + 1] = h2u(hB);
            aPl[kc][hi + 0] = h2u(lA);  aPl[kc][hi + 1] = h2u(lB);
        }
        #pragma unroll
        for (int db = 0; db < 8; ++db) {
            o[db][0] *= c0; o[db][1] *= c0; o[db][2] *= c1; o[db][3] *= c1;
        }

        // ---- GEMM2: O += Ph*V + Pl*V ----
        #pragma unroll
        for (int db2 = 0; db2 < 4; ++db2) {
            uint32_t bv[4][4];
            #pragma unroll
            for (int kc = 0; kc < 4; ++kc) {
                int row = kc * 16 + (gl << 3) + lr;
                int ch  = 2 * db2 + gh;
                ldsm4t(bv[kc], VHa + swoff(row, ch));
            }
            #pragma unroll
            for (int kc = 0; kc < 4; ++kc) {
                hmma(o[2 * db2],     aPh[kc], bv[kc][0], bv[kc][1]);
                hmma(o[2 * db2],     aPl[kc], bv[kc][0], bv[kc][1]);
                hmma(o[2 * db2 + 1], aPh[kc], bv[kc][2], bv[kc][3]);
                hmma(o[2 * db2 + 1], aPl[kc], bv[kc][2], bv[kc][3]);
            }
        }
    }

    // ---- epilogue ----
    l0 += __shfl_xor_sync(0xffffffffu, l0, 1);
    l0 += __shfl_xor_sync(0xffffffffu, l0, 2);
    l1 += __shfl_xor_sync(0xffffffffu, l1, 1);
    l1 += __shfl_xor_sync(0xffffffffu, l1, 2);
    const float inv0 = 1.0f / l0, inv1 = 1.0f / l1;

    const int r0 = q0 + w * 16 + (lane >> 2);
    const int dc = 2 * (lane & 3);
    float* O0 = Out + ((size_t)b * LQ + r0) * DD;
    float* O1 = O0 + 8 * DD;
    #pragma unroll
    for (int db = 0; db < 8; ++db) {
        *(float2*)(O0 + db * 8 + dc) = make_float2(o[db][0] * inv0, o[db][1] * inv0);
        *(float2*)(O1 + db * 8 + dc) = make_float2(o[db][2] * inv1, o[db][3] * inv1);
    }
}

extern "C" void kernel_launch(void* const* d_in, const int* in_sizes, int n_in,
                              void* d_out, int out_size)
{
    const float* Q     = (const float*)d_in[0];
    const float* K     = (const float*)d_in[1];
    const float* V     = (const float*)d_in[2];
    const float* scale = (const float*)d_in[3];
    float* O           = (float*)d_out;

    cudaFuncSetAttribute(fattn_hmma, cudaFuncAttributeMaxDynamicSharedMemorySize, SM_TOTAL);
    dim3 grid(LQ / BMq, B_);
    fattn_hmma<<<grid, 128, SM_TOTAL>>>(Q, K, V, scale, O);
}

// round 8
// speedup vs baseline: 3.8861x; 1.0039x over previous
#include <cuda_runtime.h>
#include <cuda_fp16.h>
#include <stdint.h>
#include <math.h>

#define B_   16
#define LQ   4096
#define LK   4096
#define DD   64
#define BMq  64
#define BN   64
#define NT   (LK / BN)

// dynamic smem layout (bytes)
#define OFF_QH 0
#define OFF_QL 8192
#define OFF_KH 16384
#define OFF_KL 24576
#define OFF_VH 32768
#define OFF_SK 40960     // raw fp32 K staging (16KB)
#define OFF_SV 57344     // raw fp32 V staging (16KB)
#define SM_TOTAL 73728   // 72KB

__device__ __forceinline__ void ldsm4(uint32_t r[4], uint32_t a) {
    asm volatile("ldmatrix.sync.aligned.m8n8.x4.shared.b16 {%0,%1,%2,%3}, [%4];"
                 : "=r"(r[0]), "=r"(r[1]), "=r"(r[2]), "=r"(r[3]) : "r"(a));
}
__device__ __forceinline__ void ldsm4t(uint32_t r[4], uint32_t a) {
    asm volatile("ldmatrix.sync.aligned.m8n8.x4.trans.shared.b16 {%0,%1,%2,%3}, [%4];"
                 : "=r"(r[0]), "=r"(r[1]), "=r"(r[2]), "=r"(r[3]) : "r"(a));
}
__device__ __forceinline__ void hmma(float c[4], const uint32_t a[4], uint32_t b0, uint32_t b1) {
    asm volatile("mma.sync.aligned.m16n8k16.row.col.f32.f16.f16.f32 "
                 "{%0,%1,%2,%3}, {%4,%5,%6,%7}, {%8,%9}, {%0,%1,%2,%3};"
                 : "+f"(c[0]), "+f"(c[1]), "+f"(c[2]), "+f"(c[3])
                 : "r"(a[0]), "r"(a[1]), "r"(a[2]), "r"(a[3]), "r"(b0), "r"(b1));
}
__device__ __forceinline__ uint32_t smem_u32(const void* p) {
    uint32_t a;
    asm("{ .reg .u64 t; cvta.to.shared.u64 t, %1; cvt.u32.u64 %0, t; }" : "=r"(a) : "l"(p));
    return a;
}
__device__ __forceinline__ void cpa16(uint32_t dst, const void* src) {
    asm volatile("cp.async.cg.shared.global [%0], [%1], 16;" :: "r"(dst), "l"(src));
}
#define CP_COMMIT() asm volatile("cp.async.commit_group;" ::: "memory")
#define CP_WAIT0()  asm volatile("cp.async.wait_group 0;" ::: "memory")

// swizzled byte offset within a 64x64 fp16 tile: row stride 128B, 16B chunks XOR by row&7
__device__ __forceinline__ uint32_t swoff(int row, int ch) {
    return (uint32_t)(row * 128 + ((ch ^ (row & 7)) << 4));
}
__device__ __forceinline__ uint32_t h2u(__half2 h) { return *reinterpret_cast<uint32_t*>(&h); }

// split 8 fp32 (two float4) -> 8 fp16 hi (uint4) + 8 fp16 residual (uint4)
__device__ __forceinline__ void split8(float4 a, float4 b, uint4* hi, uint4* lo) {
    __half2 h0 = __floats2half2_rn(a.x, a.y), h1 = __floats2half2_rn(a.z, a.w);
    __half2 h2 = __floats2half2_rn(b.x, b.y), h3 = __floats2half2_rn(b.z, b.w);
    float2 f0 = __half22float2(h0), f1 = __half22float2(h1);
    float2 f2 = __half22float2(h2), f3 = __half22float2(h3);
    __half2 l0 = __floats2half2_rn(a.x - f0.x, a.y - f0.y);
    __half2 l1 = __floats2half2_rn(a.z - f1.x, a.w - f1.y);
    __half2 l2 = __floats2half2_rn(b.x - f2.x, b.y - f2.y);
    __half2 l3 = __floats2half2_rn(b.z - f3.x, b.w - f3.y);
    *hi = make_uint4(h2u(h0), h2u(h1), h2u(h2), h2u(h3));
    *lo = make_uint4(h2u(l0), h2u(l1), h2u(l2), h2u(l3));
}

__global__ __launch_bounds__(128, 3)
void fattn_hmma(const float* __restrict__ Qp, const float* __restrict__ Kp,
                const float* __restrict__ Vp, const float* __restrict__ scale,
                float* __restrict__ Out)
{
    extern __shared__ __align__(128) uint8_t sm[];
    const uint32_t sb = smem_u32(sm);
    const uint32_t QHa = sb + OFF_QH, QLa = sb + OFF_QL;
    const uint32_t KHa = sb + OFF_KH, KLa = sb + OFF_KL, VHa = sb + OFF_VH;

    const int tid  = threadIdx.x;
    const int w    = tid >> 5;
    const int lane = tid & 31;
    const int gh   = (lane >> 4) & 1;
    const int gl   = (lane >> 3) & 1;
    const int lr   = lane & 7;
    const int b    = blockIdx.y;
    const int q0   = blockIdx.x * BMq;

    const float inv_scale = 1.0f / scale[0];

    const float* Qg = Qp + ((size_t)b * LQ + q0) * DD;
    const float* Kg = Kp + (size_t)b * LK * DD;
    const float* Vg = Vp + (size_t)b * LK * DD;

    // ---- prologue: prefetch tile 0 K/V into raw staging ----
    // ownership invariant: thread stages the SAME 32B segments (base*32) that
    // it will read in the convert phase -> next-tile prefetch is race-free.
    #pragma unroll
    for (int i = 0; i < 4; ++i) {
        const int base = tid + i * 128;        // 32B segment id 0..511
        cpa16(sb + OFF_SK + base * 32,      Kg + base * 8);
        cpa16(sb + OFF_SK + base * 32 + 16, Kg + base * 8 + 4);
        cpa16(sb + OFF_SV + base * 32,      Vg + base * 8);
        cpa16(sb + OFF_SV + base * 32 + 16, Vg + base * 8 + 4);
    }
    CP_COMMIT();

    // ---- Q load + split into resident QH/QL smem (8 floats / iter) ----
    #pragma unroll
    for (int i = 0; i < 4; ++i) {
        int seg = tid + i * 128;               // 0..511, 8-float segment
        int row = seg >> 3, c8 = seg & 7;
        uint32_t off = (uint32_t)(row * 128 + ((c8 ^ (row & 7)) << 4));
        float4 a = *(const float4*)(Qg + (size_t)row * DD + c8 * 8);
        float4 c = *(const float4*)(Qg + (size_t)row * DD + c8 * 8 + 4);
        uint4 hi, lo;
        split8(a, c, &hi, &lo);
        *(uint4*)(sm + OFF_QH + off) = hi;
        *(uint4*)(sm + OFF_QL + off) = lo;
    }

    float o[8][4];
    #pragma unroll
    for (int i = 0; i < 8; ++i) { o[i][0] = o[i][1] = o[i][2] = o[i][3] = 0.0f; }
    float m0 = -INFINITY, m1 = -INFINITY, l0 = 0.0f, l1 = 0.0f;

    for (int t = 0; t < NT; ++t) {
        CP_WAIT0();           // this tile's raw K/V arrived
        __syncthreads();      // all warps done reading previous fp16 tiles (and Q stores on t=0)

        // ---- convert OWN staged segments -> fp16 KH/KL/VH ----
        #pragma unroll
        for (int i = 0; i < 4; ++i) {
            int seg = tid + i * 128;
            int row = seg >> 3, c8 = seg & 7;
            uint32_t off = (uint32_t)(row * 128 + ((c8 ^ (row & 7)) << 4));
            float4 ka = *(const float4*)(sm + OFF_SK + seg * 32);
            float4 kb = *(const float4*)(sm + OFF_SK + seg * 32 + 16);
            uint4 hi, lo;
            split8(ka, kb, &hi, &lo);
            *(uint4*)(sm + OFF_KH + off) = hi;
            *(uint4*)(sm + OFF_KL + off) = lo;
            float4 va = *(const float4*)(sm + OFF_SV + seg * 32);
            float4 vb = *(const float4*)(sm + OFF_SV + seg * 32 + 16);
            __half2 v0 = __floats2half2_rn(va.x, va.y), v1 = __floats2half2_rn(va.z, va.w);
            __half2 v2 = __floats2half2_rn(vb.x, vb.y), v3 = __floats2half2_rn(vb.z, vb.w);
            *(uint4*)(sm + OFF_VH + off) = make_uint4(h2u(v0), h2u(v1), h2u(v2), h2u(v3));
        }

        // ---- prefetch next tile into staging (own segments just consumed) ----
        if (t + 1 < NT) {
            const float* Kn = Kg + (size_t)(t + 1) * BN * DD;
            const float* Vn = Vg + (size_t)(t + 1) * BN * DD;
            #pragma unroll
            for (int i = 0; i < 4; ++i) {
                const int base = tid + i * 128;
                cpa16(sb + OFF_SK + base * 32,      Kn + base * 8);
                cpa16(sb + OFF_SK + base * 32 + 16, Kn + base * 8 + 4);
                cpa16(sb + OFF_SV + base * 32,      Vn + base * 8);
                cpa16(sb + OFF_SV + base * 32 + 16, Vn + base * 8 + 4);
            }
        }
        CP_COMMIT();
        __syncthreads();      // fp16 areas ready for all warps

        // ---- Q A-fragments (from resident smem) ----
        uint32_t aQh[4][4], aQl[4][4];
        #pragma unroll
        for (int kc = 0; kc < 4; ++kc) {
            int row = w * 16 + (gl << 3) + lr;
            int ch  = 2 * kc + gh;
            ldsm4(aQh[kc], QHa + swoff(row, ch));
            ldsm4(aQl[kc], QLa + swoff(row, ch));
        }

        // ---- GEMM1: S = Qh*Kh^T + Ql*Kh^T + Qh*Kl^T ----
        float s[8][4];
        #pragma unroll
        for (int nb2 = 0; nb2 < 4; ++nb2) {
            uint32_t bh[4][4], bl[4][4];
            #pragma unroll
            for (int kc = 0; kc < 4; ++kc) {
                int row = nb2 * 16 + (gh << 3) + lr;
                int ch  = 2 * kc + gl;
                ldsm4(bh[kc], KHa + swoff(row, ch));
                ldsm4(bl[kc], KLa + swoff(row, ch));
            }
            float* cA = s[2 * nb2];
            float* cB = s[2 * nb2 + 1];
            cA[0] = cA[1] = cA[2] = cA[3] = 0.0f;
            cB[0] = cB[1] = cB[2] = cB[3] = 0.0f;
            #pragma unroll
            for (int kc = 0; kc < 4; ++kc) {
                hmma(cA, aQh[kc], bh[kc][0], bh[kc][1]);
                hmma(cA, aQl[kc], bh[kc][0], bh[kc][1]);
                hmma(cA, aQh[kc], bl[kc][0], bl[kc][1]);
                hmma(cB, aQh[kc], bh[kc][2], bh[kc][3]);
                hmma(cB, aQl[kc], bh[kc][2], bh[kc][3]);
                hmma(cB, aQh[kc], bl[kc][2], bl[kc][3]);
            }
        }

        // ---- online softmax (thread owns rows r, r+8; cols across quad lanes) ----
        float mx0 = -INFINITY, mx1 = -INFINITY;
        #pragma unroll
        for (int nb = 0; nb < 8; ++nb) {
            s[nb][0] *= inv_scale; s[nb][1] *= inv_scale;
            s[nb][2] *= inv_scale; s[nb][3] *= inv_scale;
            mx0 = fmaxf(mx0, fmaxf(s[nb][0], s[nb][1]));
            mx1 = fmaxf(mx1, fmaxf(s[nb][2], s[nb][3]));
        }
        mx0 = fmaxf(mx0, __shfl_xor_sync(0xffffffffu, mx0, 1));
        mx0 = fmaxf(mx0, __shfl_xor_sync(0xffffffffu, mx0, 2));
        mx1 = fmaxf(mx1, __shfl_xor_sync(0xffffffffu, mx1, 1));
        mx1 = fmaxf(mx1, __shfl_xor_sync(0xffffffffu, mx1, 2));
        const float mn0 = fmaxf(m0, mx0), mn1 = fmaxf(m1, mx1);
        const float c0 = __expf(m0 - mn0), c1 = __expf(m1 - mn1);
        m0 = mn0; m1 = mn1;
        l0 *= c0;  l1 *= c1;

        uint32_t aPh[4][4];
        #pragma unroll
        for (int nb = 0; nb < 8; ++nb) {
            float p0 = __expf(s[nb][0] - mn0), p1 = __expf(s[nb][1] - mn0);
            float p2 = __expf(s[nb][2] - mn1), p3 = __expf(s[nb][3] - mn1);
            l0 += p0 + p1;  l1 += p2 + p3;
            const int kc = nb >> 1, hi = (nb & 1) * 2;
            aPh[kc][hi + 0] = h2u(__floats2half2_rn(p0, p1));
            aPh[kc][hi + 1] = h2u(__floats2half2_rn(p2, p3));
        }
        #pragma unroll
        for (int db = 0; db < 8; ++db) {
            o[db][0] *= c0; o[db][1] *= c0; o[db][2] *= c1; o[db][3] *= c1;
        }

        // ---- GEMM2: O += Ph*V ----
        #pragma unroll
        for (int db2 = 0; db2 < 4; ++db2) {
            uint32_t bv[4][4];
            #pragma unroll
            for (int kc = 0; kc < 4; ++kc) {
                int row = kc * 16 + (gl << 3) + lr;
                int ch  = 2 * db2 + gh;
                ldsm4t(bv[kc], VHa + swoff(row, ch));
            }
            #pragma unroll
            for (int kc = 0; kc < 4; ++kc) {
                hmma(o[2 * db2],     aPh[kc], bv[kc][0], bv[kc][1]);
                hmma(o[2 * db2 + 1], aPh[kc], bv[kc][2], bv[kc][3]);
            }
        }
    }

    // ---- epilogue ----
    l0 += __shfl_xor_sync(0xffffffffu, l0, 1);
    l0 += __shfl_xor_sync(0xffffffffu, l0, 2);
    l1 += __shfl_xor_sync(0xffffffffu, l1, 1);
    l1 += __shfl_xor_sync(0xffffffffu, l1, 2);
    const float inv0 = 1.0f / l0, inv1 = 1.0f / l1;

    const int r0 = q0 + w * 16 + (lane >> 2);
    const int dc = 2 * (lane & 3);
    float* O0 = Out + ((size_t)b * LQ + r0) * DD;
    float* O1 = O0 + 8 * DD;
    #pragma unroll
    for (int db = 0; db < 8; ++db) {
        *(float2*)(O0 + db * 8 + dc) = make_float2(o[db][0] * inv0, o[db][1] * inv0);
        *(float2*)(O1 + db * 8 + dc) = make_float2(o[db][2] * inv1, o[db][3] * inv1);
    }
}

extern "C" void kernel_launch(void* const* d_in, const int* in_sizes, int n_in,
                              void* d_out, int out_size)
{
    const float* Q     = (const float*)d_in[0];
    const float* K     = (const float*)d_in[1];
    const float* V     = (const float*)d_in[2];
    const float* scale = (const float*)d_in[3];
    float* O           = (float*)d_out;

    cudaFuncSetAttribute(fattn_hmma, cudaFuncAttributeMaxDynamicSharedMemorySize, SM_TOTAL);
    dim3 grid(LQ / BMq, B_);
    fattn_hmma<<<grid, 128, SM_TOTAL>>>(Q, K, V, scale, O);
}

// round 9
// speedup vs baseline: 5.5529x; 1.4289x over previous
#include <cuda_runtime.h>
#include <cuda_fp16.h>
#include <stdint.h>
#include <math.h>

#define B_   16
#define LQ   4096
#define LK   4096
#define DD   64
#define BMq  64
#define BN   64
#define NT   (LK / BN)

// ---- global fp16 scratch: pre-converted, pre-swizzled tile images ----
// per (b,t) tile: 8KB block, byte-identical to the smem tile layout.
#define TILE_BYTES 8192
__device__ __align__(128) uint4 KHg[(size_t)B_ * NT * TILE_BYTES / 16];
__device__ __align__(128) uint4 KLg[(size_t)B_ * NT * TILE_BYTES / 16];
__device__ __align__(128) uint4 VHg[(size_t)B_ * NT * TILE_BYTES / 16];

// main-kernel smem layout (bytes)
#define OFF_QH  0
#define OFF_QL  8192
#define OFF_KH0 16384
#define OFF_KH1 24576
#define OFF_KL0 32768
#define OFF_KL1 40960
#define OFF_VH0 49152
#define OFF_VH1 57344
#define SM_TOTAL 65536

__device__ __forceinline__ void ldsm4(uint32_t r[4], uint32_t a) {
    asm volatile("ldmatrix.sync.aligned.m8n8.x4.shared.b16 {%0,%1,%2,%3}, [%4];"
                 : "=r"(r[0]), "=r"(r[1]), "=r"(r[2]), "=r"(r[3]) : "r"(a));
}
__device__ __forceinline__ void ldsm4t(uint32_t r[4], uint32_t a) {
    asm volatile("ldmatrix.sync.aligned.m8n8.x4.trans.shared.b16 {%0,%1,%2,%3}, [%4];"
                 : "=r"(r[0]), "=r"(r[1]), "=r"(r[2]), "=r"(r[3]) : "r"(a));
}
__device__ __forceinline__ void hmma(float c[4], const uint32_t a[4], uint32_t b0, uint32_t b1) {
    asm volatile("mma.sync.aligned.m16n8k16.row.col.f32.f16.f16.f32 "
                 "{%0,%1,%2,%3}, {%4,%5,%6,%7}, {%8,%9}, {%0,%1,%2,%3};"
                 : "+f"(c[0]), "+f"(c[1]), "+f"(c[2]), "+f"(c[3])
                 : "r"(a[0]), "r"(a[1]), "r"(a[2]), "r"(a[3]), "r"(b0), "r"(b1));
}
__device__ __forceinline__ uint32_t smem_u32(const void* p) {
    uint32_t a;
    asm("{ .reg .u64 t; cvta.to.shared.u64 t, %1; cvt.u32.u64 %0, t; }" : "=r"(a) : "l"(p));
    return a;
}
__device__ __forceinline__ void cpa16(uint32_t dst, const void* src) {
    asm volatile("cp.async.cg.shared.global [%0], [%1], 16;" :: "r"(dst), "l"(src));
}
#define CP_COMMIT() asm volatile("cp.async.commit_group;" ::: "memory")
#define CP_WAIT0()  asm volatile("cp.async.wait_group 0;" ::: "memory")

// swizzled byte offset within a 64x64 fp16 tile: row stride 128B, 16B chunks XOR by row&7
__device__ __forceinline__ uint32_t swoff(int row, int ch) {
    return (uint32_t)(row * 128 + ((ch ^ (row & 7)) << 4));
}
__device__ __forceinline__ uint32_t h2u(__half2 h) { return *reinterpret_cast<uint32_t*>(&h); }

// split 8 fp32 -> 8 fp16 hi + 8 fp16 residual
__device__ __forceinline__ void split8(float4 a, float4 b, uint4* hi, uint4* lo) {
    __half2 h0 = __floats2half2_rn(a.x, a.y), h1 = __floats2half2_rn(a.z, a.w);
    __half2 h2 = __floats2half2_rn(b.x, b.y), h3 = __floats2half2_rn(b.z, b.w);
    float2 f0 = __half22float2(h0), f1 = __half22float2(h1);
    float2 f2 = __half22float2(h2), f3 = __half22float2(h3);
    __half2 l0 = __floats2half2_rn(a.x - f0.x, a.y - f0.y);
    __half2 l1 = __floats2half2_rn(a.z - f1.x, a.w - f1.y);
    __half2 l2 = __floats2half2_rn(b.x - f2.x, b.y - f2.y);
    __half2 l3 = __floats2half2_rn(b.z - f3.x, b.w - f3.y);
    *hi = make_uint4(h2u(h0), h2u(h1), h2u(h2), h2u(h3));
    *lo = make_uint4(h2u(l0), h2u(l1), h2u(l2), h2u(l3));
}

// ---- pre-pass: convert K -> (KH, KL), V -> VH, tile-image swizzled layout ----
__global__ __launch_bounds__(128)
void prepass(const float* __restrict__ Kp, const float* __restrict__ Vp)
{
    const int t = blockIdx.x, b = blockIdx.y, tid = threadIdx.x;
    const float* Kt = Kp + ((size_t)b * LK + (size_t)t * BN) * DD;
    const float* Vt = Vp + ((size_t)b * LK + (size_t)t * BN) * DD;
    uint8_t* kh = (uint8_t*)KHg + (size_t)(b * NT + t) * TILE_BYTES;
    uint8_t* kl = (uint8_t*)KLg + (size_t)(b * NT + t) * TILE_BYTES;
    uint8_t* vh = (uint8_t*)VHg + (size_t)(b * NT + t) * TILE_BYTES;

    #pragma unroll
    for (int i = 0; i < 4; ++i) {
        int seg = tid + i * 128;              // 8-float segment, 0..511
        int row = seg >> 3, c8 = seg & 7;
        uint32_t off = (uint32_t)(row * 128 + ((c8 ^ (row & 7)) << 4));
        float4 ka = *(const float4*)(Kt + (size_t)row * DD + c8 * 8);
        float4 kb = *(const float4*)(Kt + (size_t)row * DD + c8 * 8 + 4);
        uint4 hi, lo;
        split8(ka, kb, &hi, &lo);
        *(uint4*)(kh + off) = hi;
        *(uint4*)(kl + off) = lo;
        float4 va = *(const float4*)(Vt + (size_t)row * DD + c8 * 8);
        float4 vb = *(const float4*)(Vt + (size_t)row * DD + c8 * 8 + 4);
        __half2 v0 = __floats2half2_rn(va.x, va.y), v1 = __floats2half2_rn(va.z, va.w);
        __half2 v2 = __floats2half2_rn(vb.x, vb.y), v3 = __floats2half2_rn(vb.z, vb.w);
        *(uint4*)(vh + off) = make_uint4(h2u(v0), h2u(v1), h2u(v2), h2u(v3));
    }
}

__global__ __launch_bounds__(128, 3)
void fattn_hmma(const float* __restrict__ Qp, const float* __restrict__ scale,
                float* __restrict__ Out)
{
    extern __shared__ __align__(128) uint8_t sm[];
    const uint32_t sb = smem_u32(sm);
    const uint32_t QHa = sb + OFF_QH, QLa = sb + OFF_QL;

    const int tid  = threadIdx.x;
    const int w    = tid >> 5;
    const int lane = tid & 31;
    const int gh   = (lane >> 4) & 1;
    const int gl   = (lane >> 3) & 1;
    const int lr   = lane & 7;
    const int b    = blockIdx.y;
    const int q0   = blockIdx.x * BMq;

    const float inv_scale = 1.0f / scale[0];
    const float* Qg = Qp + ((size_t)b * LQ + q0) * DD;

    const uint8_t* khg = (const uint8_t*)KHg + (size_t)b * NT * TILE_BYTES;
    const uint8_t* klg = (const uint8_t*)KLg + (size_t)b * NT * TILE_BYTES;
    const uint8_t* vhg = (const uint8_t*)VHg + (size_t)b * NT * TILE_BYTES;

    // ---- prologue: prefetch tile 0 into buffer 0 ----
    #pragma unroll
    for (int i = 0; i < 4; ++i) {
        const int c = (tid + i * 128) * 16;    // byte offset 0..8191
        cpa16(sb + OFF_KH0 + c, khg + c);
        cpa16(sb + OFF_KL0 + c, klg + c);
        cpa16(sb + OFF_VH0 + c, vhg + c);
    }
    CP_COMMIT();

    // ---- Q load + split into resident QH/QL smem ----
    #pragma unroll
    for (int i = 0; i < 4; ++i) {
        int seg = tid + i * 128;
        int row = seg >> 3, c8 = seg & 7;
        uint32_t off = (uint32_t)(row * 128 + ((c8 ^ (row & 7)) << 4));
        float4 a = *(const float4*)(Qg + (size_t)row * DD + c8 * 8);
        float4 c = *(const float4*)(Qg + (size_t)row * DD + c8 * 8 + 4);
        uint4 hi, lo;
        split8(a, c, &hi, &lo);
        *(uint4*)(sm + OFF_QH + off) = hi;
        *(uint4*)(sm + OFF_QL + off) = lo;
    }

    float o[8][4];
    #pragma unroll
    for (int i = 0; i < 8; ++i) { o[i][0] = o[i][1] = o[i][2] = o[i][3] = 0.0f; }
    float m0 = -INFINITY, m1 = -INFINITY, l0 = 0.0f, l1 = 0.0f;

    for (int t = 0; t < NT; ++t) {
        CP_WAIT0();           // tile t data landed in buf t&1
        __syncthreads();      // all warps done with tile t-1 (frees buf (t+1)&1); Q stores visible on t=0

        // ---- prefetch tile t+1 into the other buffer (overlaps compute) ----
        if (t + 1 < NT) {
            const uint32_t kh_n = sb + ((t + 1) & 1 ? OFF_KH1 : OFF_KH0);
            const uint32_t kl_n = sb + ((t + 1) & 1 ? OFF_KL1 : OFF_KL0);
            const uint32_t vh_n = sb + ((t + 1) & 1 ? OFF_VH1 : OFF_VH0);
            const uint8_t* khs = khg + (size_t)(t + 1) * TILE_BYTES;
            const uint8_t* kls = klg + (size_t)(t + 1) * TILE_BYTES;
            const uint8_t* vhs = vhg + (size_t)(t + 1) * TILE_BYTES;
            #pragma unroll
            for (int i = 0; i < 4; ++i) {
                const int c = (tid + i * 128) * 16;
                cpa16(kh_n + c, khs + c);
                cpa16(kl_n + c, kls + c);
                cpa16(vh_n + c, vhs + c);
            }
        }
        CP_COMMIT();

        const uint32_t KHa = sb + (t & 1 ? OFF_KH1 : OFF_KH0);
        const uint32_t KLa = sb + (t & 1 ? OFF_KL1 : OFF_KL0);
        const uint32_t VHa = sb + (t & 1 ? OFF_VH1 : OFF_VH0);

        // ---- Q A-fragments ----
        uint32_t aQh[4][4], aQl[4][4];
        #pragma unroll
        for (int kc = 0; kc < 4; ++kc) {
            int row = w * 16 + (gl << 3) + lr;
            int ch  = 2 * kc + gh;
            ldsm4(aQh[kc], QHa + swoff(row, ch));
            ldsm4(aQl[kc], QLa + swoff(row, ch));
        }

        // ---- GEMM1: S = Qh*Kh^T + Ql*Kh^T + Qh*Kl^T ----
        float s[8][4];
        #pragma unroll
        for (int nb2 = 0; nb2 < 4; ++nb2) {
            uint32_t bh[4][4], bl[4][4];
            #pragma unroll
            for (int kc = 0; kc < 4; ++kc) {
                int row = nb2 * 16 + (gh << 3) + lr;
                int ch  = 2 * kc + gl;
                ldsm4(bh[kc], KHa + swoff(row, ch));
                ldsm4(bl[kc], KLa + swoff(row, ch));
            }
            float* cA = s[2 * nb2];
            float* cB = s[2 * nb2 + 1];
            cA[0] = cA[1] = cA[2] = cA[3] = 0.0f;
            cB[0] = cB[1] = cB[2] = cB[3] = 0.0f;
            #pragma unroll
            for (int kc = 0; kc < 4; ++kc) {
                hmma(cA, aQh[kc], bh[kc][0], bh[kc][1]);
                hmma(cA, aQl[kc], bh[kc][0], bh[kc][1]);
                hmma(cA, aQh[kc], bl[kc][0], bl[kc][1]);
                hmma(cB, aQh[kc], bh[kc][2], bh[kc][3]);
                hmma(cB, aQl[kc], bh[kc][2], bh[kc][3]);
                hmma(cB, aQh[kc], bl[kc][2], bl[kc][3]);
            }
        }

        // ---- online softmax ----
        float mx0 = -INFINITY, mx1 = -INFINITY;
        #pragma unroll
        for (int nb = 0; nb < 8; ++nb) {
            s[nb][0] *= inv_scale; s[nb][1] *= inv_scale;
            s[nb][2] *= inv_scale; s[nb][3] *= inv_scale;
            mx0 = fmaxf(mx0, fmaxf(s[nb][0], s[nb][1]));
            mx1 = fmaxf(mx1, fmaxf(s[nb][2], s[nb][3]));
        }
        mx0 = fmaxf(mx0, __shfl_xor_sync(0xffffffffu, mx0, 1));
        mx0 = fmaxf(mx0, __shfl_xor_sync(0xffffffffu, mx0, 2));
        mx1 = fmaxf(mx1, __shfl_xor_sync(0xffffffffu, mx1, 1));
        mx1 = fmaxf(mx1, __shfl_xor_sync(0xffffffffu, mx1, 2));
        const float mn0 = fmaxf(m0, mx0), mn1 = fmaxf(m1, mx1);
        const float c0 = __expf(m0 - mn0), c1 = __expf(m1 - mn1);
        m0 = mn0; m1 = mn1;
        l0 *= c0;  l1 *= c1;

        uint32_t aPh[4][4];
        #pragma unroll
        for (int nb = 0; nb < 8; ++nb) {
            float p0 = __expf(s[nb][0] - mn0), p1 = __expf(s[nb][1] - mn0);
            float p2 = __expf(s[nb][2] - mn1), p3 = __expf(s[nb][3] - mn1);
            l0 += p0 + p1;  l1 += p2 + p3;
            const int kc = nb >> 1, hi = (nb & 1) * 2;
            aPh[kc][hi + 0] = h2u(__floats2half2_rn(p0, p1));
            aPh[kc][hi + 1] = h2u(__floats2half2_rn(p2, p3));
        }
        #pragma unroll
        for (int db = 0; db < 8; ++db) {
            o[db][0] *= c0; o[db][1] *= c0; o[db][2] *= c1; o[db][3] *= c1;
        }

        // ---- GEMM2: O += Ph*V ----
        #pragma unroll
        for (int db2 = 0; db2 < 4; ++db2) {
            uint32_t bv[4][4];
            #pragma unroll
            for (int kc = 0; kc < 4; ++kc) {
                int row = kc * 16 + (gl << 3) + lr;
                int ch  = 2 * db2 + gh;
                ldsm4t(bv[kc], VHa + swoff(row, ch));
            }
            #pragma unroll
            for (int kc = 0; kc < 4; ++kc) {
                hmma(o[2 * db2],     aPh[kc], bv[kc][0], bv[kc][1]);
                hmma(o[2 * db2 + 1], aPh[kc], bv[kc][2], bv[kc][3]);
            }
        }
    }

    // ---- epilogue ----
    l0 += __shfl_xor_sync(0xffffffffu, l0, 1);
    l0 += __shfl_xor_sync(0xffffffffu, l0, 2);
    l1 += __shfl_xor_sync(0xffffffffu, l1, 1);
    l1 += __shfl_xor_sync(0xffffffffu, l1, 2);
    const float inv0 = 1.0f / l0, inv1 = 1.0f / l1;

    const int r0 = q0 + w * 16 + (lane >> 2);
    const int dc = 2 * (lane & 3);
    float* O0 = Out + ((size_t)b * LQ + r0) * DD;
    float* O1 = O0 + 8 * DD;
    #pragma unroll
    for (int db = 0; db < 8; ++db) {
        *(float2*)(O0 + db * 8 + dc) = make_float2(o[db][0] * inv0, o[db][1] * inv0);
        *(float2*)(O1 + db * 8 + dc) = make_float2(o[db][2] * inv1, o[db][3] * inv1);
    }
}

extern "C" void kernel_launch(void* const* d_in, const int* in_sizes, int n_in,
                              void* d_out, int out_size)
{
    const float* Q     = (const float*)d_in[0];
    const float* K     = (const float*)d_in[1];
    const float* V     = (const float*)d_in[2];
    const float* scale = (const float*)d_in[3];
    float* O           = (float*)d_out;

    cudaFuncSetAttribute(fattn_hmma, cudaFuncAttributeMaxDynamicSharedMemorySize, SM_TOTAL);

    dim3 pgrid(NT, B_);
    prepass<<<pgrid, 128>>>(K, V);

    dim3 grid(LQ / BMq, B_);
    fattn_hmma<<<grid, 128, SM_TOTAL>>>(Q, scale, O);
}